// round 17
// baseline (speedup 1.0000x reference)
#include <cuda_runtime.h>
#include <cuda_bf16.h>
#include <math.h>

// Problem constants
#define BB 2
#define SS 2048
#define DD 256
#define HH 8
#define FF 1024
#define DK 32
#define LL 3
#define BS (BB*SS)            // 4096 rows
#define BHS (BB*HH*SS)        // 32768 query slots
#define NEG_MAX (-3.402823466e38f)
#define SCALE 0.17677669529663687f   // 1/sqrt(32)
#define NCHUNK 4
#define CHUNK (SS/NCHUNK)     // 512 keys per split-KV chunk

typedef unsigned int uint32;

// ---------------- device scratch (static: no allocations allowed) ----------------
__device__ float g_x  [BS*DD];           // residual stream fp32
__device__ float g_t  [BS*DD];           // pre-LN temp fp32
__device__ __nv_bfloat16 g_xh[BS*DD], g_xl[BS*DD];      // x hi/lo
__device__ __nv_bfloat16 g_oh[BS*DD], g_ol[BS*DD];      // attn out hi/lo
__device__ __nv_bfloat16 g_hidh[BS*FF], g_hidl[BS*FF];  // FFN hidden hi/lo
__device__ unsigned int g_mpk[BB*SS*SS/32];             // packed mask bits
__device__ __nv_bfloat16 g_qh[BS*DD];    // Q bf16 [bh][s][dk]
__device__ __nv_bfloat16 g_kh[BS*DD];    // K bf16 [bh][s][dk]
__device__ __nv_bfloat16 g_vh[BS*DD];    // V bf16 transposed [bh][dk][s]
// split-KV partials + completion counters (zero-init; combiner resets -> replay-safe)
__device__ float g_pm[NCHUNK*BHS], g_pl[NCHUNK*BHS];
__device__ float g_pacc[(size_t)NCHUNK*BHS*DK];
__device__ unsigned int g_cnt[BB*HH*32];
// split/transposed weights: layout [n][k], hi/lo
__device__ __nv_bfloat16 Wqkv_h[LL*768*DD], Wqkv_l[LL*768*DD];
__device__ __nv_bfloat16 Wo_h [LL*DD*DD],  Wo_l [LL*DD*DD];
__device__ __nv_bfloat16 W1_h [LL*FF*DD],  W1_l [LL*FF*DD];
__device__ __nv_bfloat16 W2_h [LL*DD*FF],  W2_l [LL*DD*FF];

// ---------------- helpers ----------------
__device__ __forceinline__ void mma_bf16(float* c, const uint32* a, const uint32* b) {
    asm volatile(
        "mma.sync.aligned.m16n8k16.row.col.f32.bf16.bf16.f32 "
        "{%0,%1,%2,%3}, {%4,%5,%6,%7}, {%8,%9}, {%0,%1,%2,%3};\n"
        : "+f"(c[0]), "+f"(c[1]), "+f"(c[2]), "+f"(c[3])
        : "r"(a[0]), "r"(a[1]), "r"(a[2]), "r"(a[3]), "r"(b[0]), "r"(b[1]));
}
__device__ __forceinline__ void ldsm4(uint32* r, uint32 addr) {
    asm volatile("ldmatrix.sync.aligned.m8n8.x4.shared.b16 {%0,%1,%2,%3}, [%4];"
        : "=r"(r[0]), "=r"(r[1]), "=r"(r[2]), "=r"(r[3]) : "r"(addr));
}
__device__ __forceinline__ uint32 pack_bf16(float lo, float hi) {
    uint32 d;
    asm("cvt.rn.bf16x2.f32 %0, %1, %2;" : "=r"(d) : "f"(hi), "f"(lo));
    return d;
}
__device__ __forceinline__ void split2(float v0, float v1, uint32& hw, uint32& lw) {
    float h0 = __bfloat162float(__float2bfloat16(v0));
    float h1 = __bfloat162float(__float2bfloat16(v1));
    hw = pack_bf16(v0, v1);
    lw = pack_bf16(v0 - h0, v1 - h1);
}
__device__ __forceinline__ void cp16(uint32 saddr, const void* gptr) {
    asm volatile("cp.async.cg.shared.global [%0], [%1], 16;\n" :: "r"(saddr), "l"(gptr));
}
__device__ __forceinline__ void cp4(uint32 saddr, const void* gptr) {
    asm volatile("cp.async.ca.shared.global [%0], [%1], 4;\n" :: "r"(saddr), "l"(gptr));
}
#define CP_COMMIT()  asm volatile("cp.async.commit_group;\n" ::: "memory")
#define CP_WAIT(n)   asm volatile("cp.async.wait_group %0;\n" :: "n"(n) : "memory")

// ---------------- merged mask pack + add-PE kernel ----------------
__global__ void __launch_bounds__(256) misc_kernel(const int* __restrict__ mask,
                                                   const float* __restrict__ x,
                                                   const float* __restrict__ pe) {
    int blk = blockIdx.x, t = threadIdx.x;
    if (blk < 1024) {                 // maskpack: 262144 words
        int w = blk * 256 + t;
        const int4* p = (const int4*)(mask) + w * 8;
        unsigned int bits = 0;
#pragma unroll
        for (int j = 0; j < 8; j++) {
            int4 v = p[j];
            bits |= (v.x != 0 ? 1u : 0u) << (j * 4 + 0);
            bits |= (v.y != 0 ? 1u : 0u) << (j * 4 + 1);
            bits |= (v.z != 0 ? 1u : 0u) << (j * 4 + 2);
            bits |= (v.w != 0 ? 1u : 0u) << (j * 4 + 3);
        }
        g_mpk[w] = bits;
    } else {                          // addpe: 1048576 elements
        int i = (blk - 1024) * 256 + t;
        float v = x[i] + pe[i & (SS*DD - 1)];
        g_x[i] = v;
        __nv_bfloat16 h = __float2bfloat16(v);
        g_xh[i] = h;
        g_xl[i] = __float2bfloat16(v - __bfloat162float(h));
    }
}

// ---------------- ONE merged weight-prep kernel (coalesced 32x32 tile transposes) ----------------
// block ranges: [0,576) qkv  [576,768) Wo  [768,1536) W1  [1536,2304) W2
__global__ void __launch_bounds__(256) wprep_kernel(
    const float* __restrict__ Wq, const float* __restrict__ Wk, const float* __restrict__ Wv,
    const float* __restrict__ Wo, const float* __restrict__ W1, const float* __restrict__ W2)
{
    __shared__ float tile[32][33];
    int id = blockIdx.x;
    int tx = threadIdx.x & 31, ty = threadIdx.x >> 5;

    const float* src; __nv_bfloat16 *dh, *dl;
    int Nsrc, k0, n0src, Kdst, n0dst;

    if (id < 576) {                                   // qkv: l(3) x (type,h)(24) x d-tile(8)
        int l = id / 192, r = id - l * 192;
        int ty2 = r / 8, xx = r - ty2 * 8;            // ty2 = type*8+h
        int type = ty2 >> 3, h = ty2 & 7;
        const float* W = (type == 0) ? Wq : ((type == 1) ? Wk : Wv);
        src = W + (size_t)l * HH * DD * DK + (size_t)h * DD * DK;
        dh = Wqkv_h + (size_t)l * 768 * DD;
        dl = Wqkv_l + (size_t)l * 768 * DD;
        Nsrc = DK; k0 = xx * 32; n0src = 0; Kdst = DD; n0dst = type * 256 + h * 32;
    } else if (id < 768) {                            // Wo: l(3) x n-tile(8) x k-tile(8)
        int id2 = id - 576;
        int l = id2 / 64, r = id2 - l * 64;
        int yy = r >> 3, xx = r & 7;
        src = Wo + (size_t)l * DD * DD;
        dh = Wo_h + (size_t)l * DD * DD; dl = Wo_l + (size_t)l * DD * DD;
        Nsrc = DD; k0 = xx * 32; n0src = yy * 32; Kdst = DD; n0dst = yy * 32;
    } else if (id < 1536) {                           // W1: l(3) x n-tile(32) x k-tile(8)
        int id2 = id - 768;
        int l = id2 / 256, r = id2 - l * 256;
        int yy = r >> 3, xx = r & 7;
        src = W1 + (size_t)l * DD * FF;
        dh = W1_h + (size_t)l * FF * DD; dl = W1_l + (size_t)l * FF * DD;
        Nsrc = FF; k0 = xx * 32; n0src = yy * 32; Kdst = DD; n0dst = yy * 32;
    } else {                                          // W2: l(3) x n-tile(8) x k-tile(32)
        int id2 = id - 1536;
        int l = id2 / 256, r = id2 - l * 256;
        int yy = r >> 5, xx = r & 31;
        src = W2 + (size_t)l * FF * DD;
        dh = W2_h + (size_t)l * DD * FF; dl = W2_l + (size_t)l * DD * FF;
        Nsrc = DD; k0 = xx * 32; n0src = yy * 32; Kdst = FF; n0dst = yy * 32;
    }

#pragma unroll
    for (int r = 0; r < 32; r += 8)
        tile[ty + r][tx] = src[(size_t)(k0 + ty + r) * Nsrc + n0src + tx];
    __syncthreads();
#pragma unroll
    for (int r = 0; r < 32; r += 8) {
        float v = tile[tx][ty + r];
        __nv_bfloat16 h = __float2bfloat16(v);
        size_t di = (size_t)(n0dst + ty + r) * Kdst + k0 + tx;
        dh[di] = h;
        dl[di] = __float2bfloat16(v - __bfloat162float(h));
    }
}

// ---------------- tensor-core split-bf16 GEMM, cp.async 2-stage + ldmatrix ----------------
#define KSTR 20   // u32 per smem row (32 bf16 + 16B pad)
#define ASZ (128*KSTR)
#define BSZ (64*KSTR)
#define SBUF (2*ASZ + 2*BSZ)          // u32 per pipeline buffer (30 KB)
#define GEMM_SMEM (2*SBUF*4)          // 60 KB dynamic smem
template<int KD, int EPI>
__global__ void __launch_bounds__(256) gemm_kernel(
    const __nv_bfloat16* __restrict__ Ah, const __nv_bfloat16* __restrict__ Al,
    const __nv_bfloat16* __restrict__ Bh, const __nv_bfloat16* __restrict__ Bl,
    const float* __restrict__ bias)
{
    extern __shared__ uint32 smem[];
    int t = threadIdx.x, lane = t & 31, w = t >> 5;
    int m0 = blockIdx.x * 128;
    int g = lane >> 2, q4 = lane & 3;
    int mw = w * 16;

    float c[8][4];
#pragma unroll
    for (int nb = 0; nb < 8; nb++) { c[nb][0] = c[nb][1] = c[nb][2] = c[nb][3] = 0.f; }

    int arow = t >> 1, ac4 = (t & 1) * 2;
    int brow = t >> 2, bc4 = t & 3;
    const uint4* gAh = (const uint4*)(Ah + (size_t)(m0 + arow) * KD);
    const uint4* gAl = (const uint4*)(Al + (size_t)(m0 + arow) * KD);
    const uint4* gBh = (const uint4*)(Bh + (size_t)((size_t)blockIdx.y * 64 + brow) * KD);
    const uint4* gBl = (const uint4*)(Bl + (size_t)((size_t)blockIdx.y * 64 + brow) * KD);
    uint32 base = (uint32)__cvta_generic_to_shared(smem);
    uint32 sA  = base + (arow * KSTR + ac4 * 4) * 4;
    uint32 sAl = sA + ASZ * 4;
    uint32 sB  = base + (2 * ASZ + brow * KSTR + bc4 * 4) * 4;
    uint32 sBl = sB + BSZ * 4;

    uint32 aAh0 = base + ((mw + (lane & 15)) * KSTR + ((lane & 16) ? 4 : 0)) * 4;
    uint32 aAl0 = aAh0 + ASZ * 4;
    uint32 aBh0 = base + (2 * ASZ + ((lane & 7) + ((lane & 16) ? 8 : 0)) * KSTR
                          + ((lane & 8) ? 4 : 0)) * 4;
    uint32 aBl0 = aBh0 + BSZ * 4;

    const int NCH = KD / 32;

    {
        cp16(sA,       gAh + ac4);     cp16(sA + 16,  gAh + ac4 + 1);
        cp16(sAl,      gAl + ac4);     cp16(sAl + 16, gAl + ac4 + 1);
        cp16(sB,       gBh + bc4);
        cp16(sBl,      gBl + bc4);
        CP_COMMIT();
    }

    for (int i = 0; i < NCH; i++) {
        int buf = i & 1;
        __syncthreads();
        if (i + 1 < NCH) {
            uint32 off = (uint32)((buf ^ 1) * SBUF * 4);
            int k8 = (i + 1) * 4;
            cp16(sA + off,       gAh + k8 + ac4);
            cp16(sA + off + 16,  gAh + k8 + ac4 + 1);
            cp16(sAl + off,      gAl + k8 + ac4);
            cp16(sAl + off + 16, gAl + k8 + ac4 + 1);
            cp16(sB + off,       gBh + k8 + bc4);
            cp16(sBl + off,      gBl + k8 + bc4);
            CP_COMMIT();
            CP_WAIT(1);
        } else {
            CP_WAIT(0);
        }
        __syncthreads();

        uint32 bufoff = (uint32)(buf * SBUF * 4);
#pragma unroll
        for (int kh = 0; kh < 2; kh++) {
            uint32 ah[4], al[4];
            ldsm4(ah, aAh0 + bufoff + kh * 32);
            ldsm4(al, aAl0 + bufoff + kh * 32);
#pragma unroll
            for (int nb2 = 0; nb2 < 4; nb2++) {
                uint32 nboff = bufoff + (uint32)(nb2 * 16 * KSTR * 4) + kh * 32;
                uint32 b4[4], bl4[4];
                ldsm4(b4,  aBh0 + nboff);
                ldsm4(bl4, aBl0 + nboff);
                mma_bf16(c[2 * nb2],     ah, b4);
                mma_bf16(c[2 * nb2],     al, b4);
                mma_bf16(c[2 * nb2],     ah, bl4);
                mma_bf16(c[2 * nb2 + 1], ah, b4 + 2);
                mma_bf16(c[2 * nb2 + 1], al, b4 + 2);
                mma_bf16(c[2 * nb2 + 1], ah, bl4 + 2);
            }
        }
    }

    int r0 = m0 + mw + g;
    if (EPI == 0) {
#pragma unroll
        for (int nb = 0; nb < 8; nb++) {
            int col = blockIdx.y * 64 + nb * 8 + 2 * q4;
            float b0 = bias[col], b1 = bias[col + 1];
            *(float2*)&g_t[(size_t)r0 * DD + col] =
                make_float2(c[nb][0] + b0, c[nb][1] + b1);
            *(float2*)&g_t[(size_t)(r0 + 8) * DD + col] =
                make_float2(c[nb][2] + b0, c[nb][3] + b1);
        }
    } else if (EPI == 1) {
#pragma unroll
        for (int nb = 0; nb < 8; nb++) {
            int col = blockIdx.y * 64 + nb * 8 + 2 * q4;
            float b0 = bias[col], b1 = bias[col + 1];
            float v0 = fmaxf(c[nb][0] + b0, 0.f), v1 = fmaxf(c[nb][1] + b1, 0.f);
            float v2 = fmaxf(c[nb][2] + b0, 0.f), v3 = fmaxf(c[nb][3] + b1, 0.f);
            uint32 hw, lw;
            split2(v0, v1, hw, lw);
            ((uint32*)g_hidh)[((size_t)r0 * FF + col) >> 1] = hw;
            ((uint32*)g_hidl)[((size_t)r0 * FF + col) >> 1] = lw;
            split2(v2, v3, hw, lw);
            ((uint32*)g_hidh)[((size_t)(r0 + 8) * FF + col) >> 1] = hw;
            ((uint32*)g_hidl)[((size_t)(r0 + 8) * FF + col) >> 1] = lw;
        }
    } else {
        int type = blockIdx.y >> 2;
        int nbase = (blockIdx.y & 3) * 64;
        int b = r0 >> 11, s0 = r0 & 2047;
#pragma unroll
        for (int nb = 0; nb < 8; nb++) {
            int nl = nbase + nb * 8 + 2 * q4;
            int h = nl >> 5, kk = nl & 31;
            if (type == 2) {
                size_t vb = ((size_t)(b * HH + h) * DK + kk) * SS;
                g_vh[vb + s0]             = __float2bfloat16(c[nb][0]);
                g_vh[vb + SS + s0]        = __float2bfloat16(c[nb][1]);
                g_vh[vb + s0 + 8]         = __float2bfloat16(c[nb][2]);
                g_vh[vb + SS + s0 + 8]    = __float2bfloat16(c[nb][3]);
            } else {
                __nv_bfloat16* dst = (type == 0) ? g_qh : g_kh;
                size_t i0 = (((size_t)(b * HH + h) * SS + s0) * DK + kk) >> 1;
                ((uint32*)dst)[i0]       = pack_bf16(c[nb][0], c[nb][1]);
                ((uint32*)dst)[i0 + 128] = pack_bf16(c[nb][2], c[nb][3]);
            }
        }
    }
}

// ------------- tensor-core flash attention, split-KV x4, cp.async 2-stage, fused combine -------------
#define KSTRIDE 20
#define VSTRIDE 36
__global__ void __launch_bounds__(128) attn_mma_kernel() {
    __shared__ uint32 Ks[2][64 * KSTRIDE];
    __shared__ uint32 Vt[2][32 * VSTRIDE];
    __shared__ uint32 Msk[2][128];
    __shared__ unsigned int s_last;

    int t = threadIdx.x;
    int lane = t & 31, w = t >> 5;
    int cid = blockIdx.x & (NCHUNK - 1);
    int qb = blockIdx.x >> 2;             // NCHUNK==4
    int bh = qb >> 5;
    int qt = qb & 31;
    int b = bh >> 3;
    int m0 = w * 16;
    int g = lane >> 2, q4 = lane & 3;

    int sq_lo = qt * 64 + m0 + g;
    const uint32* qrow_lo = (const uint32*)(g_qh + ((size_t)bh * SS + sq_lo) * DK);
    const uint32* qrow_hi = qrow_lo + 8 * (DK / 2);
    uint32 aq[2][4];
#pragma unroll
    for (int kk = 0; kk < 2; kk++) {
        int base = kk * 8 + q4;
        aq[kk][0] = qrow_lo[base];     aq[kk][1] = qrow_hi[base];
        aq[kk][2] = qrow_lo[base + 4]; aq[kk][3] = qrow_hi[base + 4];
    }

    float mr_lo = -INFINITY, mr_hi = -INFINITY, l_lo = 0.f, l_hi = 0.f;
    float o[4][4];
#pragma unroll
    for (int jn = 0; jn < 4; jn++)
#pragma unroll
        for (int e = 0; e < 4; e++) o[jn][e] = 0.f;

    const float4* ksrc = (const float4*)(g_kh + (size_t)bh * SS * DK);
    const unsigned int* mbase = g_mpk + (size_t)(b * SS + qt * 64) * (SS / 32);

    int krow = t >> 2, kc4 = t & 3;
    int vrow_s = t >> 3, vc4 = t & 7;
    uint32 ks0 = (uint32)__cvta_generic_to_shared(&Ks[0][krow * KSTRIDE + kc4 * 4]);
    uint32 ks1 = (uint32)__cvta_generic_to_shared(&Ks[0][(krow + 32) * KSTRIDE + kc4 * 4]);
    uint32 vs0 = (uint32)__cvta_generic_to_shared(&Vt[0][vrow_s * VSTRIDE + vc4 * 4]);
    uint32 vs1 = (uint32)__cvta_generic_to_shared(&Vt[0][(vrow_s + 16) * VSTRIDE + vc4 * 4]);
    uint32 ms0 = (uint32)__cvta_generic_to_shared(&Msk[0][t]);
    const uint32 kbufsz = (uint32)(64 * KSTRIDE * 4);
    const uint32 vbufsz = (uint32)(32 * VSTRIDE * 4);

    int kstart = cid * CHUNK;
    const int NT = CHUNK / 64;

    {
        int k0 = kstart;
        cp16(ks0, ksrc + k0 * 4 + t);
        cp16(ks1, ksrc + k0 * 4 + t + 128);
        cp16(vs0, (const float4*)(g_vh + ((size_t)bh * DK + vrow_s) * SS + k0) + vc4);
        cp16(vs1, (const float4*)(g_vh + ((size_t)bh * DK + vrow_s + 16) * SS + k0) + vc4);
        cp4(ms0, mbase + (size_t)(t >> 1) * (SS / 32) + (k0 >> 5) + (t & 1));
        CP_COMMIT();
    }

    for (int i = 0; i < NT; i++) {
        int buf = i & 1;
        __syncthreads();
        if (i + 1 < NT) {
            int k0 = kstart + (i + 1) * 64;
            uint32 off = (buf ^ 1) ? 1u : 0u;
            cp16(ks0 + off * kbufsz, ksrc + k0 * 4 + t);
            cp16(ks1 + off * kbufsz, ksrc + k0 * 4 + t + 128);
            cp16(vs0 + off * vbufsz, (const float4*)(g_vh + ((size_t)bh * DK + vrow_s) * SS + k0) + vc4);
            cp16(vs1 + off * vbufsz, (const float4*)(g_vh + ((size_t)bh * DK + vrow_s + 16) * SS + k0) + vc4);
            cp4(ms0 + off * 512u, mbase + (size_t)(t >> 1) * (SS / 32) + (k0 >> 5) + (t & 1));
            CP_COMMIT();
            CP_WAIT(1);
        } else {
            CP_WAIT(0);
        }
        __syncthreads();

        float c[8][4];
#pragma unroll
        for (int j = 0; j < 8; j++) { c[j][0] = c[j][1] = c[j][2] = c[j][3] = 0.f; }
#pragma unroll
        for (int j = 0; j < 8; j++) {
            int kr = (8 * j + g) * KSTRIDE;
            uint32 bfr[2];
            bfr[0] = Ks[buf][kr + q4];     bfr[1] = Ks[buf][kr + q4 + 4];
            mma_bf16(c[j], aq[0], bfr);
            bfr[0] = Ks[buf][kr + 8 + q4]; bfr[1] = Ks[buf][kr + 8 + q4 + 4];
            mma_bf16(c[j], aq[1], bfr);
        }
        uint32 ml0 = Msk[buf][(m0 + g) * 2],     ml1 = Msk[buf][(m0 + g) * 2 + 1];
        uint32 mh0 = Msk[buf][(m0 + g + 8) * 2], mh1 = Msk[buf][(m0 + g + 8) * 2 + 1];
#pragma unroll
        for (int j = 0; j < 8; j++) {
#pragma unroll
            for (int e = 0; e < 2; e++) {
                int bit = 8 * j + 2 * q4 + e;
                uint32 wl = (bit < 32) ? ml0 : ml1;
                uint32 wh = (bit < 32) ? mh0 : mh1;
                int bp = bit & 31;
                c[j][e]     = ((wl >> bp) & 1u) ? NEG_MAX : c[j][e] * SCALE;
                c[j][2 + e] = ((wh >> bp) & 1u) ? NEG_MAX : c[j][2 + e] * SCALE;
            }
        }
        float mx_lo = c[0][0], mx_hi = c[0][2];
#pragma unroll
        for (int j = 0; j < 8; j++) {
            mx_lo = fmaxf(mx_lo, fmaxf(c[j][0], c[j][1]));
            mx_hi = fmaxf(mx_hi, fmaxf(c[j][2], c[j][3]));
        }
        mx_lo = fmaxf(mx_lo, __shfl_xor_sync(0xffffffffu, mx_lo, 1));
        mx_lo = fmaxf(mx_lo, __shfl_xor_sync(0xffffffffu, mx_lo, 2));
        mx_hi = fmaxf(mx_hi, __shfl_xor_sync(0xffffffffu, mx_hi, 1));
        mx_hi = fmaxf(mx_hi, __shfl_xor_sync(0xffffffffu, mx_hi, 2));
        float mn_lo = fmaxf(mr_lo, mx_lo), mn_hi = fmaxf(mr_hi, mx_hi);
        float corr_lo = __expf(mr_lo - mn_lo), corr_hi = __expf(mr_hi - mn_hi);
        mr_lo = mn_lo; mr_hi = mn_hi;

        float sum_lo = 0.f, sum_hi = 0.f;
#pragma unroll
        for (int j = 0; j < 8; j++) {
            c[j][0] = __expf(c[j][0] - mn_lo); sum_lo += c[j][0];
            c[j][1] = __expf(c[j][1] - mn_lo); sum_lo += c[j][1];
            c[j][2] = __expf(c[j][2] - mn_hi); sum_hi += c[j][2];
            c[j][3] = __expf(c[j][3] - mn_hi); sum_hi += c[j][3];
        }
        sum_lo += __shfl_xor_sync(0xffffffffu, sum_lo, 1);
        sum_lo += __shfl_xor_sync(0xffffffffu, sum_lo, 2);
        sum_hi += __shfl_xor_sync(0xffffffffu, sum_hi, 1);
        sum_hi += __shfl_xor_sync(0xffffffffu, sum_hi, 2);
        l_lo = l_lo * corr_lo + sum_lo;
        l_hi = l_hi * corr_hi + sum_hi;
#pragma unroll
        for (int jn = 0; jn < 4; jn++) {
            o[jn][0] *= corr_lo; o[jn][1] *= corr_lo;
            o[jn][2] *= corr_hi; o[jn][3] *= corr_hi;
        }
        uint32 pf[4][4];
#pragma unroll
        for (int jj = 0; jj < 4; jj++) {
            pf[jj][0] = pack_bf16(c[2 * jj][0],     c[2 * jj][1]);
            pf[jj][1] = pack_bf16(c[2 * jj][2],     c[2 * jj][3]);
            pf[jj][2] = pack_bf16(c[2 * jj + 1][0], c[2 * jj + 1][1]);
            pf[jj][3] = pack_bf16(c[2 * jj + 1][2], c[2 * jj + 1][3]);
        }
#pragma unroll
        for (int jn = 0; jn < 4; jn++) {
            int vr = (8 * jn + g) * VSTRIDE;
#pragma unroll
            for (int jj = 0; jj < 4; jj++) {
                uint32 bfr[2];
                bfr[0] = Vt[buf][vr + 8 * jj + q4];
                bfr[1] = Vt[buf][vr + 8 * jj + q4 + 4];
                mma_bf16(o[jn], pf[jj], bfr);
            }
        }
    }
    // store unnormalized partials
    int qidx = bh * SS + sq_lo;       // rows qidx, qidx+8
    float* pp = g_pacc + ((size_t)cid * BHS + qidx) * DK;
#pragma unroll
    for (int jn = 0; jn < 4; jn++) {
        int col = 8 * jn + 2 * q4;
        *(float2*)&pp[col]          = make_float2(o[jn][0], o[jn][1]);
        *(float2*)&pp[8 * DK + col] = make_float2(o[jn][2], o[jn][3]);
    }
    if (q4 == 0) {
        g_pm[cid * BHS + qidx] = mr_lo;     g_pl[cid * BHS + qidx] = l_lo;
        g_pm[cid * BHS + qidx + 8] = mr_hi; g_pl[cid * BHS + qidx + 8] = l_hi;
    }

    // ---- last-arriving block combines all NCHUNK partials for this q-tile ----
    __threadfence();
    if (t == 0) s_last = atomicAdd(&g_cnt[qb], 1u);
    __syncthreads();
    if (s_last == NCHUNK - 1) {
        if (t == 0) g_cnt[qb] = 0;                       // reset for next use/replay
        int h = bh & 7;
        for (int idx = t; idx < 64 * 8; idx += 128) {    // 64 queries x 8 float4
            int ql = idx >> 3, i = idx & 7;
            int qq = bh * SS + qt * 64 + ql;
            float gm = -INFINITY;
#pragma unroll
            for (int c2 = 0; c2 < NCHUNK; c2++) gm = fmaxf(gm, g_pm[c2 * BHS + qq]);
            float wgt[NCHUNK];
            float L = 0.f;
#pragma unroll
            for (int c2 = 0; c2 < NCHUNK; c2++) {
                wgt[c2] = __expf(g_pm[c2 * BHS + qq] - gm);
                L += g_pl[c2 * BHS + qq] * wgt[c2];
            }
            float inv = 1.f / L;
#pragma unroll
            for (int c2 = 0; c2 < NCHUNK; c2++) wgt[c2] *= inv;

            float r0 = 0.f, r1 = 0.f, r2 = 0.f, r3 = 0.f;
#pragma unroll
            for (int c2 = 0; c2 < NCHUNK; c2++) {
                float4 a = ((const float4*)(g_pacc + ((size_t)c2 * BHS + qq) * DK))[i];
                r0 = fmaf(a.x, wgt[c2], r0); r1 = fmaf(a.y, wgt[c2], r1);
                r2 = fmaf(a.z, wgt[c2], r2); r3 = fmaf(a.w, wgt[c2], r3);
            }
            size_t obase = ((size_t)b * SS + qt * 64 + ql) * DD + h * DK;
            uint32 hw, lw;
            split2(r0, r1, hw, lw);
            ((uint32*)g_oh)[(obase >> 1) + i * 2] = hw;
            ((uint32*)g_ol)[(obase >> 1) + i * 2] = lw;
            split2(r2, r3, hw, lw);
            ((uint32*)g_oh)[(obase >> 1) + i * 2 + 1] = hw;
            ((uint32*)g_ol)[(obase >> 1) + i * 2 + 1] = lw;
        }
    }
}

// residual + layernorm: warp per row, 8 rows/block, shfl-only reductions.
__global__ void __launch_bounds__(256) ln_kernel(const float* __restrict__ gam,
                                                 const float* __restrict__ bet,
                                                 float* __restrict__ outp) {
    int lane = threadIdx.x & 31, wrp = threadIdx.x >> 5;
    int row = blockIdx.x * 8 + wrp;
    const float4* t4 = (const float4*)(g_t + (size_t)row * DD) + lane * 2;
    const float4* x4 = (const float4*)(g_x + (size_t)row * DD) + lane * 2;
    float4 a0 = t4[0], a1 = t4[1], b0 = x4[0], b1 = x4[1];
    float v[8] = { a0.x + b0.x, a0.y + b0.y, a0.z + b0.z, a0.w + b0.w,
                   a1.x + b1.x, a1.y + b1.y, a1.z + b1.z, a1.w + b1.w };
    float s = 0.f;
#pragma unroll
    for (int i = 0; i < 8; i++) s += v[i];
#pragma unroll
    for (int o = 16; o; o >>= 1) s += __shfl_xor_sync(0xffffffffu, s, o);
    float mu = s * (1.f / DD);
    float s2 = 0.f;
#pragma unroll
    for (int i = 0; i < 8; i++) { float d = v[i] - mu; s2 += d * d; }
#pragma unroll
    for (int o = 16; o; o >>= 1) s2 += __shfl_xor_sync(0xffffffffu, s2, o);
    float rstd = rsqrtf(s2 * (1.f / DD) + 1e-7f);

    const float4* g4 = (const float4*)gam + lane * 2;
    const float4* be4 = (const float4*)bet + lane * 2;
    float4 gg0 = g4[0], gg1 = g4[1], bb0 = be4[0], bb1 = be4[1];
    float out[8];
    out[0] = (v[0] - mu) * rstd * gg0.x + bb0.x;
    out[1] = (v[1] - mu) * rstd * gg0.y + bb0.y;
    out[2] = (v[2] - mu) * rstd * gg0.z + bb0.z;
    out[3] = (v[3] - mu) * rstd * gg0.w + bb0.w;
    out[4] = (v[4] - mu) * rstd * gg1.x + bb1.x;
    out[5] = (v[5] - mu) * rstd * gg1.y + bb1.y;
    out[6] = (v[6] - mu) * rstd * gg1.z + bb1.z;
    out[7] = (v[7] - mu) * rstd * gg1.w + bb1.w;

    if (outp) {
        float4* oo = (float4*)(outp + (size_t)row * DD) + lane * 2;
        oo[0] = make_float4(out[0], out[1], out[2], out[3]);
        oo[1] = make_float4(out[4], out[5], out[6], out[7]);
    } else {
        float4* xo = (float4*)(g_x + (size_t)row * DD) + lane * 2;
        xo[0] = make_float4(out[0], out[1], out[2], out[3]);
        xo[1] = make_float4(out[4], out[5], out[6], out[7]);
        uint32 hw[4], lw[4];
#pragma unroll
        for (int i = 0; i < 4; i++) split2(out[2 * i], out[2 * i + 1], hw[i], lw[i]);
        size_t wi = ((size_t)row * DD) / 2 + lane * 4;
        *(uint4*)((uint32*)g_xh + wi) = *(uint4*)hw;
        *(uint4*)((uint32*)g_xl + wi) = *(uint4*)lw;
    }
}

// ---------------- launch ----------------
extern "C" void kernel_launch(void* const* d_in, const int* in_sizes, int n_in,
                              void* d_out, int out_size) {
    const float* x  = (const float*)d_in[0];
    const int*   mask = (const int*)d_in[1];     // jnp bool promoted to int32
    const float* pe = (const float*)d_in[2];
    const float* Wq = (const float*)d_in[3];
    const float* Wk = (const float*)d_in[4];
    const float* Wv = (const float*)d_in[5];
    const float* Wo = (const float*)d_in[6];
    const float* bo = (const float*)d_in[7];
    const float* ln1_g = (const float*)d_in[8];
    const float* ln1_b = (const float*)d_in[9];
    const float* W1 = (const float*)d_in[10];
    const float* b1 = (const float*)d_in[11];
    const float* W2 = (const float*)d_in[12];
    const float* b2 = (const float*)d_in[13];
    const float* ln2_g = (const float*)d_in[14];
    const float* ln2_b = (const float*)d_in[15];

    void *p_xh, *p_xl, *p_oh, *p_ol, *p_hh, *p_hl;
    void *p_wqkvh, *p_wqkvl, *p_woh, *p_wol, *p_w1h, *p_w1l, *p_w2h, *p_w2l;
    cudaGetSymbolAddress(&p_xh, g_xh);   cudaGetSymbolAddress(&p_xl, g_xl);
    cudaGetSymbolAddress(&p_oh, g_oh);   cudaGetSymbolAddress(&p_ol, g_ol);
    cudaGetSymbolAddress(&p_hh, g_hidh); cudaGetSymbolAddress(&p_hl, g_hidl);
    cudaGetSymbolAddress(&p_wqkvh, Wqkv_h); cudaGetSymbolAddress(&p_wqkvl, Wqkv_l);
    cudaGetSymbolAddress(&p_woh, Wo_h);  cudaGetSymbolAddress(&p_wol, Wo_l);
    cudaGetSymbolAddress(&p_w1h, W1_h);  cudaGetSymbolAddress(&p_w1l, W1_l);
    cudaGetSymbolAddress(&p_w2h, W2_h);  cudaGetSymbolAddress(&p_w2l, W2_l);
    const __nv_bfloat16 *xh = (const __nv_bfloat16*)p_xh, *xl = (const __nv_bfloat16*)p_xl;
    const __nv_bfloat16 *oh = (const __nv_bfloat16*)p_oh, *ol = (const __nv_bfloat16*)p_ol;
    const __nv_bfloat16 *hh = (const __nv_bfloat16*)p_hh, *hl = (const __nv_bfloat16*)p_hl;

    cudaFuncSetAttribute(gemm_kernel<256, 0>,  cudaFuncAttributeMaxDynamicSharedMemorySize, GEMM_SMEM);
    cudaFuncSetAttribute(gemm_kernel<256, 1>,  cudaFuncAttributeMaxDynamicSharedMemorySize, GEMM_SMEM);
    cudaFuncSetAttribute(gemm_kernel<256, 2>,  cudaFuncAttributeMaxDynamicSharedMemorySize, GEMM_SMEM);
    cudaFuncSetAttribute(gemm_kernel<1024, 0>, cudaFuncAttributeMaxDynamicSharedMemorySize, GEMM_SMEM);

    // prep: 2 launches total
    wprep_kernel<<<2304, 256>>>(Wq, Wk, Wv, Wo, W1, W2);
    misc_kernel<<<1024 + 4096, 256>>>(mask, x, pe);

    for (int l = 0; l < LL; l++) {
        const __nv_bfloat16* wqh = (const __nv_bfloat16*)p_wqkvh + (size_t)l * 768 * DD;
        const __nv_bfloat16* wql = (const __nv_bfloat16*)p_wqkvl + (size_t)l * 768 * DD;
        const __nv_bfloat16* woh2 = (const __nv_bfloat16*)p_woh + (size_t)l * DD * DD;
        const __nv_bfloat16* wol2 = (const __nv_bfloat16*)p_wol + (size_t)l * DD * DD;
        const __nv_bfloat16* w1h2 = (const __nv_bfloat16*)p_w1h + (size_t)l * FF * DD;
        const __nv_bfloat16* w1l2 = (const __nv_bfloat16*)p_w1l + (size_t)l * FF * DD;
        const __nv_bfloat16* w2h2 = (const __nv_bfloat16*)p_w2h + (size_t)l * DD * FF;
        const __nv_bfloat16* w2l2 = (const __nv_bfloat16*)p_w2l + (size_t)l * DD * FF;

        gemm_kernel<256, 2><<<dim3(32, 12), 256, GEMM_SMEM>>>(xh, xl, wqh, wql, nullptr);       // QKV
        attn_mma_kernel<<<BB * HH * (SS / 64) * NCHUNK, 128>>>();                               // + combine
        gemm_kernel<256, 0><<<dim3(32, 4), 256, GEMM_SMEM>>>(oh, ol, woh2, wol2, bo + l * DD);  // Wo
        ln_kernel<<<BS / 8, 256>>>(ln1_g + l * DD, ln1_b + l * DD, nullptr);
        gemm_kernel<256, 1><<<dim3(32, 16), 256, GEMM_SMEM>>>(xh, xl, w1h2, w1l2, b1 + l * FF); // FFN1
        gemm_kernel<1024, 0><<<dim3(32, 4), 256, GEMM_SMEM>>>(hh, hl, w2h2, w2l2, b2 + l * DD); // FFN2
        ln_kernel<<<BS / 8, 256>>>(ln2_g + l * DD, ln2_b + l * DD,
                                   (l == LL - 1) ? (float*)d_out : nullptr);
    }
}